// round 15
// baseline (speedup 1.0000x reference)
#include <cuda_runtime.h>
#include <cuda_bf16.h>
#include <cstdint>

#define N_NODES  50000
#define N_EDGES  800000
#define E_TOT    850000
#define IN_F     768
#define HID2     128
#define NHID     64
#define N_GRAPHS 128
#define CSR_NB   64
#define NPB      782
#define MR       64

// ---------------- scratch (device globals; no runtime allocation) ----------
__device__ __nv_bfloat16 g_xwb[(size_t)N_NODES * HID2];
__device__ __nv_bfloat16 g_h1h[(size_t)N_NODES * HID2];
__device__ __nv_bfloat16 g_w1h[(size_t)HID2 * IN_F];
__device__ __nv_bfloat16 g_w2h[(size_t)HID2 * HID2];
__device__ float g_pool[N_GRAPHS * HID2];   // fused mean-pool accumulator
__device__ float g_es[N_NODES];
__device__ float g_ed[N_NODES];
__device__ int   g_rowptr[N_NODES + 1];
__device__ int   g_counts[N_NODES];
__device__ int   g_fill[N_NODES];
__device__ int   g_srcidx[E_TOT];
__device__ int   g_blksum[CSR_NB];
__device__ volatile int g_bar[3];
__device__ int   g_is64;

// ---------------- helpers ----------------------------------------------------
__device__ __forceinline__ float selu_f(float x) {
    const float sc = 1.0507009873554805f, al = 1.6732632423543772f;
    return x > 0.f ? sc * x : sc * al * expm1f(x);
}
__device__ __forceinline__ float lrelu02(float x) { return x > 0.f ? x : 0.2f * x; }
__device__ __forceinline__ uint32_t pack_bf2(float a, float b) {
    __nv_bfloat162 p(__float2bfloat16(a), __float2bfloat16(b));
    return *(uint32_t*)&p;
}
__device__ __forceinline__ int batch_at(const int* b, int i) {
    return g_is64 ? (int)((const long long*)b)[i] : b[i];
}

// ---------------- prep: weight transpose + pool zero + dtype + bar reset -----
// blocks [0,384): W1; [384,448): W2; 448: dtype+bars; [449,513): zero g_pool
__global__ void k_prep(const int* __restrict__ ei,
                       const float* __restrict__ W1, const float* __restrict__ W2) {
    int b = blockIdx.x, t = threadIdx.x;
    if (b < 384) {
        int idx = b * 256 + t;
        int n = idx & (HID2 - 1), k = idx >> 7;
        g_w1h[(size_t)n * IN_F + k] = __float2bfloat16(W1[(size_t)k * HID2 + n]);
    } else if (b < 448) {
        int idx = (b - 384) * 256 + t;
        int n = idx & (HID2 - 1), k = idx >> 7;
        g_w2h[(size_t)n * HID2 + k] = __float2bfloat16(W2[(size_t)k * HID2 + n]);
    } else if (b == 448) {
        if (t < 32) {
            int nz = (ei[2 * t + 1] != 0) ? 1 : 0;
            uint32_t bal = __ballot_sync(0xffffffffu, nz);
            if (t == 0) g_is64 = (bal == 0u) ? 1 : 0;
        } else if (t >= 32 && t < 35) {
            g_bar[t - 32] = 0;
        }
    } else {
        int idx = (b - 449) * 256 + t;        // 64 blocks x 256 = 16384
        g_pool[idx] = 0.f;
    }
}

// ---------------- spin barrier across the CSR_NB co-resident blocks ----------
__device__ __forceinline__ void csr_bar(int i) {
    __syncthreads();
    if (threadIdx.x == 0) {
        __threadfence();
        atomicAdd((int*)&g_bar[i], 1);
        while (g_bar[i] < CSR_NB) { }
        __threadfence();
    }
    __syncthreads();
}

// ---------------- mma / ldmatrix / cp.async primitives -----------------------
__device__ __forceinline__ void mma16816(float* c, const uint32_t* a, const uint32_t* b) {
    asm volatile(
        "mma.sync.aligned.m16n8k16.row.col.f32.bf16.bf16.f32 "
        "{%0,%1,%2,%3}, {%4,%5,%6,%7}, {%8,%9}, {%0,%1,%2,%3};"
        : "+f"(c[0]), "+f"(c[1]), "+f"(c[2]), "+f"(c[3])
        : "r"(a[0]), "r"(a[1]), "r"(a[2]), "r"(a[3]), "r"(b[0]), "r"(b[1]));
}
#define LDMX4(r, addr) \
    asm volatile("ldmatrix.sync.aligned.m8n8.x4.shared.b16 {%0,%1,%2,%3}, [%4];" \
        : "=r"((r)[0]), "=r"((r)[1]), "=r"((r)[2]), "=r"((r)[3]) : "r"(addr))
#define CP16(dst, src) \
    asm volatile("cp.async.cg.shared.global [%0], [%1], 16;" \
        :: "r"(dst), "l"(src) : "memory")
#define CP_COMMIT() asm volatile("cp.async.commit_group;" ::: "memory")
#define CP_WAIT0()  asm volatile("cp.async.wait_group 0;" ::: "memory")

__device__ __forceinline__ uint32_t smem_u32(const void* p) {
    uint32_t a;
    asm("{ .reg .u64 t; cvta.to.shared.u64 t, %1; cvt.u32.u64 %0, t; }"
        : "=r"(a) : "l"(p));
    return a;
}

// ---- K-chunk 64: row stride 72 bf16 = 144B (=36 words ≡ 4 mod 32, conflict-free)
#define RB      144
#define ATILE_B (64 * RB)            // 9216
#define BTILE_B (128 * RB)           // 18432
#define OFF_B   ATILE_B
#define BUFB    (ATILE_B + BTILE_B)  // 27648
#define GEMM_DSMEM (2 * BUFB)        // 55296 -> 3 CTA/SM

// AF=1: A fp32 staged+converted (layer 1); AF=0: A bf16 via cp.async (layer 2).
template <int AF>
__global__ __launch_bounds__(256, 3) void k_gemm_mma(
    const float* __restrict__ Af, const __nv_bfloat16* __restrict__ Abh,
    const __nv_bfloat16* __restrict__ Bh,
    int M, int K,
    const float* __restrict__ a_s, const float* __restrict__ a_d,
    __nv_bfloat16* __restrict__ xwb,
    int csr_blocks, const int* __restrict__ ei)
{
    // ============ CSR worker blocks ============
    if ((int)blockIdx.x < csr_blocks) {
        int b = blockIdx.x, t = threadIdx.x;
        int is64 = g_is64;
        for (int e = b * 256 + t; e < N_EDGES; e += CSR_NB * 256) {
            int dst = is64 ? (int)((const long long*)ei)[(size_t)N_EDGES + e]
                           : ei[(size_t)N_EDGES + e];
            atomicAdd(&g_counts[dst], 1);
        }
        csr_bar(0);
        __shared__ int sh[256];
        __shared__ int s_pre;
        int start = b * NPB;
        int end = min(start + NPB, N_NODES);
        int i0 = start + t * 4;
        int c[4];
        int s = 0;
#pragma unroll
        for (int j = 0; j < 4; j++) {
            int i = i0 + j;
            c[j] = (i < end) ? g_counts[i] + 1 : 0;
            s += c[j];
        }
        sh[t] = s;
        __syncthreads();
        for (int off = 1; off < 256; off <<= 1) {
            int add = (t >= off) ? sh[t - off] : 0;
            __syncthreads();
            sh[t] += add;
            __syncthreads();
        }
        int excl = sh[t] - s;
        int total = sh[255];
        if (t == 0) g_blksum[b] = total;
        csr_bar(1);
        if (t == 0) {
            int p = 0;
            for (int bb = 0; bb < b; bb++) p += g_blksum[bb];
            s_pre = p;
        }
        __syncthreads();
        int off = s_pre + excl;
#pragma unroll
        for (int j = 0; j < 4; j++) {
            int i = i0 + j;
            if (i < end) {
                g_rowptr[i] = off;
                g_srcidx[off] = i;
                g_fill[i] = off + 1;
                g_counts[i] = 0;
                off += c[j];
            }
        }
        if (b == CSR_NB - 1 && t == 0) g_rowptr[N_NODES] = s_pre + total;
        csr_bar(2);
        for (int e = b * 256 + t; e < N_EDGES; e += CSR_NB * 256) {
            int src, dst;
            if (is64) {
                src = (int)((const long long*)ei)[e];
                dst = (int)((const long long*)ei)[(size_t)N_EDGES + e];
            } else {
                src = ei[e];
                dst = ei[(size_t)N_EDGES + e];
            }
            g_srcidx[atomicAdd(&g_fill[dst], 1)] = src;
        }
        return;
    }

    // ============ GEMM blocks: 64 rows x 128 cols, K-chunk 64 ============
    extern __shared__ __align__(16) char dsm[];
    __shared__ float s_es[MR], s_ed[MR];

    int tid = threadIdx.x, lane = tid & 31, w = tid >> 5;
    int wm = w & 1, wn = w >> 1;
    int block_row = (blockIdx.x - csr_blocks) * MR;
    int q = lane >> 2, qr = lane & 3;
    uint32_t base = smem_u32(dsm);

    float acc[2][4][4];
#pragma unroll
    for (int i = 0; i < 2; i++)
#pragma unroll
        for (int j = 0; j < 4; j++)
#pragma unroll
            for (int v = 0; v < 4; v++) acc[i][j][v] = 0.f;

    float4 pAf[4];
    const int nchunks = K >> 6;

#define ISSUE_CP(c, buf) do {                                                   \
    int _k0 = (c) << 6;                                                         \
    uint32_t _dbu = base + (buf) * BUFB;                                        \
    _Pragma("unroll")                                                           \
    for (int it = 0; it < 4; it++) {                                            \
        int idx = tid + it * 256;                                               \
        int row = idx >> 3, cg = idx & 7;                                       \
        uint32_t _o = (uint32_t)(row * RB + cg * 16);                           \
        CP16(_dbu + OFF_B + _o, Bh + (size_t)row * K + _k0 + cg * 8);           \
    }                                                                           \
    if (!AF) {                                                                  \
        _Pragma("unroll")                                                       \
        for (int it = 0; it < 2; it++) {                                        \
            int idx = tid + it * 256;                                           \
            int row = idx >> 3, cg = idx & 7;                                   \
            int grow = block_row + row;                                         \
            if (grow >= M) grow = M - 1;                                        \
            CP16(_dbu + (uint32_t)(row * RB + cg * 16),                         \
                 Abh + (size_t)grow * K + _k0 + cg * 8);                        \
        }                                                                       \
    }                                                                           \
    CP_COMMIT(); } while (0)

#define LDG_A(c) do {                                                           \
    int _k0 = (c) << 6;                                                         \
    _Pragma("unroll")                                                           \
    for (int it = 0; it < 4; it++) {                                            \
        int idx = tid + it * 256;                                               \
        int row = idx >> 4, col = (idx & 15) * 4;                               \
        int grow = block_row + row;                                             \
        if (grow >= M) grow = M - 1;                                            \
        pAf[it] = *(const float4*)(Af + (size_t)grow * K + _k0 + col);          \
    } } while (0)

#define STS_A(buf) do {                                                         \
    char* _db = dsm + (buf) * BUFB;                                             \
    _Pragma("unroll")                                                           \
    for (int it = 0; it < 4; it++) {                                            \
        int idx = tid + it * 256;                                               \
        int row = idx >> 4, col = (idx & 15) * 4;                               \
        uint32_t _o = (uint32_t)(row * RB + col * 2);                           \
        float4 v = pAf[it];                                                     \
        uint2 uh;                                                               \
        uh.x = pack_bf2(v.x, v.y); uh.y = pack_bf2(v.z, v.w);                   \
        *(uint2*)(_db + _o) = uh;                                               \
    } } while (0)

    // prologue: start A DRAM fetch first, then B copies
    if (AF) LDG_A(0);
    ISSUE_CP(0, 0);
    if (AF) STS_A(0);
    CP_WAIT0();
    __syncthreads();

    for (int c = 0; c < nchunks; c++) {
        int cb = c & 1;
        if (c + 1 < nchunks) {
            if (AF) LDG_A(c + 1);     // A DRAM fetch issued before B cp.async
            ISSUE_CP(c + 1, !cb);
        }
        uint32_t bA = base + cb * BUFB;
        uint32_t bB = bA + OFF_B;
#pragma unroll
        for (int ks = 0; ks < 64; ks += 16) {
            uint32_t ah[2][4];
#pragma unroll
            for (int i = 0; i < 2; i++) {
                int row = wm * 32 + i * 16 + (lane & 15);
                int col = ks + ((lane >> 4) << 3);
                LDMX4(ah[i], bA + (uint32_t)(row * RB + col * 2));
            }
#pragma unroll
            for (int jp = 0; jp < 2; jp++) {
                int nrow = wn * 32 + jp * 16 + ((lane >> 4) << 3) + (lane & 7);
                int col  = ks + (((lane >> 3) & 1) << 3);
                uint32_t bh[4];
                LDMX4(bh, bB + (uint32_t)(nrow * RB + col * 2));
#pragma unroll
                for (int i = 0; i < 2; i++) {
                    mma16816(acc[i][2 * jp],     ah[i], bh);
                    mma16816(acc[i][2 * jp + 1], ah[i], bh + 2);
                }
            }
        }
        if (c + 1 < nchunks) {
            if (AF) STS_A(!cb);
            CP_WAIT0();
        }
        __syncthreads();
    }

    // ---- epilogue: store xw (bf16) + fused es/ed (fp32) ----
    if (tid < MR) { s_es[tid] = 0.f; s_ed[tid] = 0.f; }
    __syncthreads();

    float2 asv[4], adv[4];
#pragma unroll
    for (int j = 0; j < 4; j++) {
        int col = wn * 32 + j * 8 + qr * 2;
        asv[j] = *(const float2*)(a_s + col);
        adv[j] = *(const float2*)(a_d + col);
    }
#pragma unroll
    for (int i = 0; i < 2; i++) {
        int lrow = wm * 32 + i * 16 + q;
        int grow0 = block_row + lrow;
        int grow1 = grow0 + 8;
        float e0s = 0.f, e0d = 0.f, e1s = 0.f, e1d = 0.f;
#pragma unroll
        for (int j = 0; j < 4; j++) {
            int col = wn * 32 + j * 8 + qr * 2;
            float d0 = acc[i][j][0], d1 = acc[i][j][1];
            float d2 = acc[i][j][2], d3 = acc[i][j][3];
            if (grow0 < M) *(uint32_t*)(xwb + (size_t)grow0 * HID2 + col) = pack_bf2(d0, d1);
            if (grow1 < M) *(uint32_t*)(xwb + (size_t)grow1 * HID2 + col) = pack_bf2(d2, d3);
            e0s += d0 * asv[j].x + d1 * asv[j].y;
            e0d += d0 * adv[j].x + d1 * adv[j].y;
            e1s += d2 * asv[j].x + d3 * asv[j].y;
            e1d += d2 * adv[j].x + d3 * adv[j].y;
        }
#pragma unroll
        for (int off = 1; off < 4; off <<= 1) {
            e0s += __shfl_xor_sync(0xffffffffu, e0s, off);
            e0d += __shfl_xor_sync(0xffffffffu, e0d, off);
            e1s += __shfl_xor_sync(0xffffffffu, e1s, off);
            e1d += __shfl_xor_sync(0xffffffffu, e1d, off);
        }
        if (qr == 0) {
            atomicAdd(&s_es[lrow], e0s);
            atomicAdd(&s_ed[lrow], e0d);
            atomicAdd(&s_es[lrow + 8], e1s);
            atomicAdd(&s_ed[lrow + 8], e1d);
        }
    }
    __syncthreads();
    if (tid < MR) {
        int grow = block_row + tid;
        if (grow < M) {
            g_es[grow] = s_es[tid];
            g_ed[grow] = s_ed[tid];
        }
    }
}

// ---------------- GAT aggregation: single pass, bf16 gather ------------------
// OUT=1: write bf16 h (feeds GEMM2). OUT=0: fused mean-pool (atomicAdd g_pool).
template <int OUT>
__global__ void k_gat_agg(const __nv_bfloat16* __restrict__ xwb,
                          const float* __restrict__ bias,
                          const int* __restrict__ batch,
                          __nv_bfloat16* __restrict__ oh)
{
    int node = (blockIdx.x * blockDim.x + threadIdx.x) >> 5;
    int lane = threadIdx.x & 31;
    if (node >= N_NODES) return;
    int beg = g_rowptr[node], end = g_rowptr[node + 1];
    float edv = g_ed[node];

    float ssum = 0.f;
    float4 acc = make_float4(0.f, 0.f, 0.f, 0.f);
    for (int base = beg; base < end; base += 32) {
        int i = base + lane;
        float alpha = 0.f;
        int sidx = 0;
        if (i < end) {
            sidx = g_srcidx[i];
            alpha = __expf(lrelu02(g_es[sidx] + edv));
        }
        ssum += alpha;
        int cnt = min(32, end - base);
        for (int j = 0; j < cnt; j++) {
            float a = __shfl_sync(0xffffffffu, alpha, j);
            int   s = __shfl_sync(0xffffffffu, sidx, j);
            uint2 u = ((const uint2*)(xwb + (size_t)s * HID2))[lane];
            float2 f0 = __bfloat1622float2(*(__nv_bfloat162*)&u.x);
            float2 f1 = __bfloat1622float2(*(__nv_bfloat162*)&u.y);
            acc.x += a * f0.x; acc.y += a * f0.y;
            acc.z += a * f1.x; acc.w += a * f1.y;
        }
    }
#pragma unroll
    for (int o = 16; o; o >>= 1) ssum += __shfl_xor_sync(0xffffffffu, ssum, o);
    float inv = 1.f / ssum;

    float4 b4 = ((const float4*)bias)[lane];
    float r0 = selu_f(acc.x * inv + b4.x), r1 = selu_f(acc.y * inv + b4.y);
    float r2 = selu_f(acc.z * inv + b4.z), r3 = selu_f(acc.w * inv + b4.w);
    if (OUT == 1) {
        uint2 uh;
        uh.x = pack_bf2(r0, r1);
        uh.y = pack_bf2(r2, r3);
        *(uint2*)(oh + (size_t)node * HID2 + lane * 4) = uh;
    } else {
        int g = batch_at(batch, node);
        float* p = g_pool + g * HID2 + lane * 4;
        atomicAdd(p + 0, r0);
        atomicAdd(p + 1, r1);
        atomicAdd(p + 2, r2);
        atomicAdd(p + 3, r3);
    }
}

// ---------------- pool-finalize + MLP + log_softmax ---------------------------
__device__ __forceinline__ int lb_batch(const int* b, int n, int v) {
    int lo = 0, hi = n;
    while (lo < hi) {
        int mid = (lo + hi) >> 1;
        if (batch_at(b, mid) < v) lo = mid + 1; else hi = mid;
    }
    return lo;
}

__global__ void k_pool_mlp(const int* __restrict__ batch,
                           const float* __restrict__ fc1w, const float* __restrict__ fc1b,
                           const float* __restrict__ fc2w, const float* __restrict__ fc2b,
                           float* __restrict__ out)
{
    int g = blockIdx.x, t = threadIdx.x;
    __shared__ float pooled[HID2];
    __shared__ float hid[NHID];
    __shared__ float logits[2];

    int lo = lb_batch(batch, N_NODES, g);
    int hi = lb_batch(batch, N_NODES, g + 1);
    float cnt = (float)max(hi - lo, 1);
    pooled[t] = selu_f(g_pool[g * HID2 + t] / cnt);
    __syncthreads();

    if (t < NHID) {
        float a = fc1b[t];
#pragma unroll 8
        for (int c = 0; c < HID2; c++) a += pooled[c] * fc1w[c * NHID + t];
        hid[t] = selu_f(a);
    }
    __syncthreads();
    if (t < 2) {
        float a = fc2b[t];
#pragma unroll 8
        for (int j = 0; j < NHID; j++) a += hid[j] * fc2w[j * 2 + t];
        logits[t] = a;
    }
    __syncthreads();
    if (t == 0) {
        float l0 = logits[0], l1 = logits[1];
        float mx = fmaxf(l0, l1);
        float lse = mx + logf(expf(l0 - mx) + expf(l1 - mx));
        out[g * 2 + 0] = l0 - lse;
        out[g * 2 + 1] = l1 - lse;
    }
}

// ---------------- launcher ----------------------------------------------------
extern "C" void kernel_launch(void* const* d_in, const int* in_sizes, int n_in,
                              void* d_out, int out_size)
{
    const float* x     = (const float*)d_in[0];
    const int*   ei    = (const int*)d_in[1];
    const int*   batch = (const int*)d_in[2];
    const float* W1    = (const float*)d_in[3];
    const float* as1   = (const float*)d_in[4];
    const float* ad1   = (const float*)d_in[5];
    const float* b1    = (const float*)d_in[6];
    const float* W2    = (const float*)d_in[7];
    const float* as2   = (const float*)d_in[8];
    const float* ad2   = (const float*)d_in[9];
    const float* b2    = (const float*)d_in[10];
    const float* fc1w  = (const float*)d_in[11];
    const float* fc1b  = (const float*)d_in[12];
    const float* fc2w  = (const float*)d_in[13];
    const float* fc2b  = (const float*)d_in[14];
    float* out = (float*)d_out;

    __nv_bfloat16 *xwb, *h1h, *w1h, *w2h;
    cudaGetSymbolAddress((void**)&xwb, g_xwb);
    cudaGetSymbolAddress((void**)&h1h, g_h1h);
    cudaGetSymbolAddress((void**)&w1h, g_w1h);
    cudaGetSymbolAddress((void**)&w2h, g_w2h);

    cudaFuncSetAttribute(k_gemm_mma<1>, cudaFuncAttributeMaxDynamicSharedMemorySize, GEMM_DSMEM);
    cudaFuncSetAttribute(k_gemm_mma<0>, cudaFuncAttributeMaxDynamicSharedMemorySize, GEMM_DSMEM);

    const int GEMM_GRID = (N_NODES + MR - 1) / MR;   // 782
    const int WARP_GRID = (N_NODES * 32 + 255) / 256;

    // --- weight transpose + pool zero + dtype + barrier reset ---
    k_prep<<<513, 256>>>(ei, W1, W2);

    // --- layer 1: CSR build (64 worker blocks) + bf16 GEMM, one kernel ---
    k_gemm_mma<1><<<CSR_NB + GEMM_GRID, 256, GEMM_DSMEM>>>(
        x, nullptr, w1h, N_NODES, IN_F, as1, ad1, xwb, CSR_NB, ei);
    k_gat_agg<1><<<WARP_GRID, 256>>>(xwb, b1, nullptr, h1h);

    // --- layer 2 ---
    k_gemm_mma<0><<<GEMM_GRID, 256, GEMM_DSMEM>>>(
        nullptr, h1h, w2h, N_NODES, HID2, as2, ad2, xwb, 0, nullptr);
    k_gat_agg<0><<<WARP_GRID, 256>>>(xwb, b2, batch, nullptr);   // fused mean-pool

    // --- pool finalize + MLP + log_softmax ---
    k_pool_mlp<<<N_GRAPHS, HID2>>>(batch, fc1w, fc1b, fc2w, fc2b, out);
}

// round 16
// speedup vs baseline: 1.2561x; 1.2561x over previous
#include <cuda_runtime.h>
#include <cuda_bf16.h>
#include <cstdint>

#define N_NODES  50000
#define N_EDGES  800000
#define E_TOT    850000
#define IN_F     768
#define HID2     128
#define NHID     64
#define N_GRAPHS 128
#define CSR_NB   64
#define NPB      782
#define MR       64

// ---------------- scratch (device globals; no runtime allocation) ----------
__device__ __nv_bfloat16 g_xwb[(size_t)N_NODES * HID2];
__device__ __nv_bfloat16 g_h1h[(size_t)N_NODES * HID2];   // layer-1 h; reused for layer-2 h
__device__ __nv_bfloat16 g_w1h[(size_t)HID2 * IN_F];
__device__ __nv_bfloat16 g_w2h[(size_t)HID2 * HID2];
__device__ float g_es[N_NODES];
__device__ float g_ed[N_NODES];
__device__ int   g_rowptr[N_NODES + 1];
__device__ int   g_counts[N_NODES];
__device__ int   g_fill[N_NODES];
__device__ int   g_srcidx[E_TOT];
__device__ int   g_blksum[CSR_NB];
__device__ volatile int g_bar[3];
__device__ int   g_is64;

// ---------------- helpers ----------------------------------------------------
__device__ __forceinline__ float selu_f(float x) {
    const float sc = 1.0507009873554805f, al = 1.6732632423543772f;
    return x > 0.f ? sc * x : sc * al * expm1f(x);
}
__device__ __forceinline__ float lrelu02(float x) { return x > 0.f ? x : 0.2f * x; }
__device__ __forceinline__ uint32_t pack_bf2(float a, float b) {
    __nv_bfloat162 p(__float2bfloat16(a), __float2bfloat16(b));
    return *(uint32_t*)&p;
}
__device__ __forceinline__ int batch_at(const int* b, int i) {
    return g_is64 ? (int)((const long long*)b)[i] : b[i];
}

// ---------------- prep: weight transpose (bf16) + dtype + barrier reset ------
__global__ void k_prep(const int* __restrict__ ei,
                       const float* __restrict__ W1, const float* __restrict__ W2) {
    int b = blockIdx.x, t = threadIdx.x;
    if (b < 384) {
        int idx = b * 256 + t;
        int n = idx & (HID2 - 1), k = idx >> 7;
        g_w1h[(size_t)n * IN_F + k] = __float2bfloat16(W1[(size_t)k * HID2 + n]);
    } else if (b < 448) {
        int idx = (b - 384) * 256 + t;
        int n = idx & (HID2 - 1), k = idx >> 7;
        g_w2h[(size_t)n * HID2 + k] = __float2bfloat16(W2[(size_t)k * HID2 + n]);
    } else {
        if (t < 32) {
            int nz = (ei[2 * t + 1] != 0) ? 1 : 0;
            uint32_t bal = __ballot_sync(0xffffffffu, nz);
            if (t == 0) g_is64 = (bal == 0u) ? 1 : 0;
        } else if (t >= 32 && t < 35) {
            g_bar[t - 32] = 0;
        }
    }
}

// ---------------- spin barrier across the CSR_NB co-resident blocks ----------
__device__ __forceinline__ void csr_bar(int i) {
    __syncthreads();
    if (threadIdx.x == 0) {
        __threadfence();
        atomicAdd((int*)&g_bar[i], 1);
        while (g_bar[i] < CSR_NB) { }
        __threadfence();
    }
    __syncthreads();
}

// ---------------- mma / ldmatrix / cp.async primitives -----------------------
__device__ __forceinline__ void mma16816(float* c, const uint32_t* a, const uint32_t* b) {
    asm volatile(
        "mma.sync.aligned.m16n8k16.row.col.f32.bf16.bf16.f32 "
        "{%0,%1,%2,%3}, {%4,%5,%6,%7}, {%8,%9}, {%0,%1,%2,%3};"
        : "+f"(c[0]), "+f"(c[1]), "+f"(c[2]), "+f"(c[3])
        : "r"(a[0]), "r"(a[1]), "r"(a[2]), "r"(a[3]), "r"(b[0]), "r"(b[1]));
}
#define LDMX4(r, addr) \
    asm volatile("ldmatrix.sync.aligned.m8n8.x4.shared.b16 {%0,%1,%2,%3}, [%4];" \
        : "=r"((r)[0]), "=r"((r)[1]), "=r"((r)[2]), "=r"((r)[3]) : "r"(addr))
#define CP16(dst, src) \
    asm volatile("cp.async.cg.shared.global [%0], [%1], 16;" \
        :: "r"(dst), "l"(src) : "memory")
#define CP_COMMIT() asm volatile("cp.async.commit_group;" ::: "memory")
#define CP_WAIT0()  asm volatile("cp.async.wait_group 0;" ::: "memory")

__device__ __forceinline__ uint32_t smem_u32(const void* p) {
    uint32_t a;
    asm("{ .reg .u64 t; cvta.to.shared.u64 t, %1; cvt.u32.u64 %0, t; }"
        : "=r"(a) : "l"(p));
    return a;
}

// ---- K-chunk 64: row stride 72 bf16 = 144B (=36 words ≡ 4 mod 32, conflict-free)
#define RB      144
#define ATILE_B (64 * RB)            // 9216
#define BTILE_B (128 * RB)           // 18432
#define OFF_B   ATILE_B
#define BUFB    (ATILE_B + BTILE_B)  // 27648
#define GEMM_DSMEM (2 * BUFB)        // 55296 -> 3 CTA/SM

// AF=1: A fp32 staged+converted (layer 1); AF=0: A bf16 via cp.async (layer 2).
template <int AF>
__global__ __launch_bounds__(256, 3) void k_gemm_mma(
    const float* __restrict__ Af, const __nv_bfloat16* __restrict__ Abh,
    const __nv_bfloat16* __restrict__ Bh,
    int M, int K,
    const float* __restrict__ a_s, const float* __restrict__ a_d,
    __nv_bfloat16* __restrict__ xwb,
    int csr_blocks, const int* __restrict__ ei)
{
    // ============ CSR worker blocks ============
    if ((int)blockIdx.x < csr_blocks) {
        int b = blockIdx.x, t = threadIdx.x;
        int is64 = g_is64;
        for (int e = b * 256 + t; e < N_EDGES; e += CSR_NB * 256) {
            int dst = is64 ? (int)((const long long*)ei)[(size_t)N_EDGES + e]
                           : ei[(size_t)N_EDGES + e];
            atomicAdd(&g_counts[dst], 1);
        }
        csr_bar(0);
        __shared__ int sh[256];
        __shared__ int s_pre;
        int start = b * NPB;
        int end = min(start + NPB, N_NODES);
        int i0 = start + t * 4;
        int c[4];
        int s = 0;
#pragma unroll
        for (int j = 0; j < 4; j++) {
            int i = i0 + j;
            c[j] = (i < end) ? g_counts[i] + 1 : 0;
            s += c[j];
        }
        sh[t] = s;
        __syncthreads();
        for (int off = 1; off < 256; off <<= 1) {
            int add = (t >= off) ? sh[t - off] : 0;
            __syncthreads();
            sh[t] += add;
            __syncthreads();
        }
        int excl = sh[t] - s;
        int total = sh[255];
        if (t == 0) g_blksum[b] = total;
        csr_bar(1);
        if (t == 0) {
            int p = 0;
            for (int bb = 0; bb < b; bb++) p += g_blksum[bb];
            s_pre = p;
        }
        __syncthreads();
        int off = s_pre + excl;
#pragma unroll
        for (int j = 0; j < 4; j++) {
            int i = i0 + j;
            if (i < end) {
                g_rowptr[i] = off;
                g_srcidx[off] = i;
                g_fill[i] = off + 1;
                g_counts[i] = 0;
                off += c[j];
            }
        }
        if (b == CSR_NB - 1 && t == 0) g_rowptr[N_NODES] = s_pre + total;
        csr_bar(2);
        for (int e = b * 256 + t; e < N_EDGES; e += CSR_NB * 256) {
            int src, dst;
            if (is64) {
                src = (int)((const long long*)ei)[e];
                dst = (int)((const long long*)ei)[(size_t)N_EDGES + e];
            } else {
                src = ei[e];
                dst = ei[(size_t)N_EDGES + e];
            }
            g_srcidx[atomicAdd(&g_fill[dst], 1)] = src;
        }
        return;
    }

    // ============ GEMM blocks: 64 rows x 128 cols, K-chunk 64 ============
    extern __shared__ __align__(16) char dsm[];
    __shared__ float s_es[MR], s_ed[MR];

    int tid = threadIdx.x, lane = tid & 31, w = tid >> 5;
    int wm = w & 1, wn = w >> 1;
    int block_row = (blockIdx.x - csr_blocks) * MR;
    int q = lane >> 2, qr = lane & 3;
    uint32_t base = smem_u32(dsm);

    float acc[2][4][4];
#pragma unroll
    for (int i = 0; i < 2; i++)
#pragma unroll
        for (int j = 0; j < 4; j++)
#pragma unroll
            for (int v = 0; v < 4; v++) acc[i][j][v] = 0.f;

    float4 pAf[4];
    const int nchunks = K >> 6;

#define ISSUE_CP(c, buf) do {                                                   \
    int _k0 = (c) << 6;                                                         \
    uint32_t _dbu = base + (buf) * BUFB;                                        \
    _Pragma("unroll")                                                           \
    for (int it = 0; it < 4; it++) {                                            \
        int idx = tid + it * 256;                                               \
        int row = idx >> 3, cg = idx & 7;                                       \
        uint32_t _o = (uint32_t)(row * RB + cg * 16);                           \
        CP16(_dbu + OFF_B + _o, Bh + (size_t)row * K + _k0 + cg * 8);           \
    }                                                                           \
    if (!AF) {                                                                  \
        _Pragma("unroll")                                                       \
        for (int it = 0; it < 2; it++) {                                        \
            int idx = tid + it * 256;                                           \
            int row = idx >> 3, cg = idx & 7;                                   \
            int grow = block_row + row;                                         \
            if (grow >= M) grow = M - 1;                                        \
            CP16(_dbu + (uint32_t)(row * RB + cg * 16),                         \
                 Abh + (size_t)grow * K + _k0 + cg * 8);                        \
        }                                                                       \
    }                                                                           \
    CP_COMMIT(); } while (0)

#define LDG_A(c) do {                                                           \
    int _k0 = (c) << 6;                                                         \
    _Pragma("unroll")                                                           \
    for (int it = 0; it < 4; it++) {                                            \
        int idx = tid + it * 256;                                               \
        int row = idx >> 4, col = (idx & 15) * 4;                               \
        int grow = block_row + row;                                             \
        if (grow >= M) grow = M - 1;                                            \
        pAf[it] = *(const float4*)(Af + (size_t)grow * K + _k0 + col);          \
    } } while (0)

#define STS_A(buf) do {                                                         \
    char* _db = dsm + (buf) * BUFB;                                             \
    _Pragma("unroll")                                                           \
    for (int it = 0; it < 4; it++) {                                            \
        int idx = tid + it * 256;                                               \
        int row = idx >> 4, col = (idx & 15) * 4;                               \
        uint32_t _o = (uint32_t)(row * RB + col * 2);                           \
        float4 v = pAf[it];                                                     \
        uint2 uh;                                                               \
        uh.x = pack_bf2(v.x, v.y); uh.y = pack_bf2(v.z, v.w);                   \
        *(uint2*)(_db + _o) = uh;                                               \
    } } while (0)

    // prologue: chunk 0 into buffer 0
    ISSUE_CP(0, 0);
    if (AF) { LDG_A(0); STS_A(0); }
    CP_WAIT0();
    __syncthreads();

    for (int c = 0; c < nchunks; c++) {
        int cb = c & 1;
        if (c + 1 < nchunks) {
            ISSUE_CP(c + 1, !cb);
            if (AF) LDG_A(c + 1);
        }
        uint32_t bA = base + cb * BUFB;
        uint32_t bB = bA + OFF_B;
#pragma unroll
        for (int ks = 0; ks < 64; ks += 16) {
            uint32_t ah[2][4];
#pragma unroll
            for (int i = 0; i < 2; i++) {
                int row = wm * 32 + i * 16 + (lane & 15);
                int col = ks + ((lane >> 4) << 3);
                LDMX4(ah[i], bA + (uint32_t)(row * RB + col * 2));
            }
#pragma unroll
            for (int jp = 0; jp < 2; jp++) {
                int nrow = wn * 32 + jp * 16 + ((lane >> 4) << 3) + (lane & 7);
                int col  = ks + (((lane >> 3) & 1) << 3);
                uint32_t bh[4];
                LDMX4(bh, bB + (uint32_t)(nrow * RB + col * 2));
#pragma unroll
                for (int i = 0; i < 2; i++) {
                    mma16816(acc[i][2 * jp],     ah[i], bh);
                    mma16816(acc[i][2 * jp + 1], ah[i], bh + 2);
                }
            }
        }
        if (c + 1 < nchunks) {
            if (AF) STS_A(!cb);
            CP_WAIT0();
        }
        __syncthreads();
    }

    // ---- epilogue: store xw (bf16) + fused es/ed (fp32) ----
    if (tid < MR) { s_es[tid] = 0.f; s_ed[tid] = 0.f; }
    __syncthreads();

    float2 asv[4], adv[4];
#pragma unroll
    for (int j = 0; j < 4; j++) {
        int col = wn * 32 + j * 8 + qr * 2;
        asv[j] = *(const float2*)(a_s + col);
        adv[j] = *(const float2*)(a_d + col);
    }
#pragma unroll
    for (int i = 0; i < 2; i++) {
        int lrow = wm * 32 + i * 16 + q;
        int grow0 = block_row + lrow;
        int grow1 = grow0 + 8;
        float e0s = 0.f, e0d = 0.f, e1s = 0.f, e1d = 0.f;
#pragma unroll
        for (int j = 0; j < 4; j++) {
            int col = wn * 32 + j * 8 + qr * 2;
            float d0 = acc[i][j][0], d1 = acc[i][j][1];
            float d2 = acc[i][j][2], d3 = acc[i][j][3];
            if (grow0 < M) *(uint32_t*)(xwb + (size_t)grow0 * HID2 + col) = pack_bf2(d0, d1);
            if (grow1 < M) *(uint32_t*)(xwb + (size_t)grow1 * HID2 + col) = pack_bf2(d2, d3);
            e0s += d0 * asv[j].x + d1 * asv[j].y;
            e0d += d0 * adv[j].x + d1 * adv[j].y;
            e1s += d2 * asv[j].x + d3 * asv[j].y;
            e1d += d2 * adv[j].x + d3 * adv[j].y;
        }
#pragma unroll
        for (int off = 1; off < 4; off <<= 1) {
            e0s += __shfl_xor_sync(0xffffffffu, e0s, off);
            e0d += __shfl_xor_sync(0xffffffffu, e0d, off);
            e1s += __shfl_xor_sync(0xffffffffu, e1s, off);
            e1d += __shfl_xor_sync(0xffffffffu, e1d, off);
        }
        if (qr == 0) {
            atomicAdd(&s_es[lrow], e0s);
            atomicAdd(&s_ed[lrow], e0d);
            atomicAdd(&s_es[lrow + 8], e1s);
            atomicAdd(&s_ed[lrow + 8], e1d);
        }
    }
    __syncthreads();
    if (tid < MR) {
        int grow = block_row + tid;
        if (grow < M) {
            g_es[grow] = s_es[tid];
            g_ed[grow] = s_ed[tid];
        }
    }
}

// ---------------- GAT aggregation: single pass, bf16 gather ------------------
// Both layers write bf16 h (layer 1 -> GEMM2 input; layer 2 -> pooled by k_pool_mlp)
__global__ void k_gat_agg(const __nv_bfloat16* __restrict__ xwb,
                          const float* __restrict__ bias,
                          __nv_bfloat16* __restrict__ oh)
{
    int node = (blockIdx.x * blockDim.x + threadIdx.x) >> 5;
    int lane = threadIdx.x & 31;
    if (node >= N_NODES) return;
    int beg = g_rowptr[node], end = g_rowptr[node + 1];
    float edv = g_ed[node];

    float ssum = 0.f;
    float4 acc = make_float4(0.f, 0.f, 0.f, 0.f);
    for (int base = beg; base < end; base += 32) {
        int i = base + lane;
        float alpha = 0.f;
        int sidx = 0;
        if (i < end) {
            sidx = g_srcidx[i];
            alpha = __expf(lrelu02(g_es[sidx] + edv));
        }
        ssum += alpha;
        int cnt = min(32, end - base);
        for (int j = 0; j < cnt; j++) {
            float a = __shfl_sync(0xffffffffu, alpha, j);
            int   s = __shfl_sync(0xffffffffu, sidx, j);
            uint2 u = ((const uint2*)(xwb + (size_t)s * HID2))[lane];
            float2 f0 = __bfloat1622float2(*(__nv_bfloat162*)&u.x);
            float2 f1 = __bfloat1622float2(*(__nv_bfloat162*)&u.y);
            acc.x += a * f0.x; acc.y += a * f0.y;
            acc.z += a * f1.x; acc.w += a * f1.y;
        }
    }
#pragma unroll
    for (int o = 16; o; o >>= 1) ssum += __shfl_xor_sync(0xffffffffu, ssum, o);
    float inv = 1.f / ssum;

    float4 b4 = ((const float4*)bias)[lane];
    float r0 = selu_f(acc.x * inv + b4.x), r1 = selu_f(acc.y * inv + b4.y);
    float r2 = selu_f(acc.z * inv + b4.z), r3 = selu_f(acc.w * inv + b4.w);
    uint2 uh;
    uh.x = pack_bf2(r0, r1);
    uh.y = pack_bf2(r2, r3);
    *(uint2*)(oh + (size_t)node * HID2 + lane * 4) = uh;
}

// ---------------- pool + MLP + log_softmax (bf16 h input) ---------------------
__device__ __forceinline__ int lb_batch(const int* b, int n, int v) {
    int lo = 0, hi = n;
    while (lo < hi) {
        int mid = (lo + hi) >> 1;
        if (batch_at(b, mid) < v) lo = mid + 1; else hi = mid;
    }
    return lo;
}

__global__ void k_pool_mlp(const __nv_bfloat16* __restrict__ h,
                           const int* __restrict__ batch,
                           const float* __restrict__ fc1w, const float* __restrict__ fc1b,
                           const float* __restrict__ fc2w, const float* __restrict__ fc2b,
                           float* __restrict__ out)
{
    int g = blockIdx.x, t = threadIdx.x;
    __shared__ float pooled[HID2];
    __shared__ float hid[NHID];
    __shared__ float logits[2];

    int lo = lb_batch(batch, N_NODES, g);
    int hi = lb_batch(batch, N_NODES, g + 1);
    float s = 0.f;
    for (int i = lo; i < hi; i++)
        s += __bfloat162float(h[(size_t)i * HID2 + t]);
    pooled[t] = selu_f(s / (float)max(hi - lo, 1));
    __syncthreads();

    if (t < NHID) {
        float a = fc1b[t];
#pragma unroll 8
        for (int c = 0; c < HID2; c++) a += pooled[c] * fc1w[c * NHID + t];
        hid[t] = selu_f(a);
    }
    __syncthreads();
    if (t < 2) {
        float a = fc2b[t];
#pragma unroll 8
        for (int j = 0; j < NHID; j++) a += hid[j] * fc2w[j * 2 + t];
        logits[t] = a;
    }
    __syncthreads();
    if (t == 0) {
        float l0 = logits[0], l1 = logits[1];
        float mx = fmaxf(l0, l1);
        float lse = mx + logf(expf(l0 - mx) + expf(l1 - mx));
        out[g * 2 + 0] = l0 - lse;
        out[g * 2 + 1] = l1 - lse;
    }
}

// ---------------- launcher ----------------------------------------------------
extern "C" void kernel_launch(void* const* d_in, const int* in_sizes, int n_in,
                              void* d_out, int out_size)
{
    const float* x     = (const float*)d_in[0];
    const int*   ei    = (const int*)d_in[1];
    const int*   batch = (const int*)d_in[2];
    const float* W1    = (const float*)d_in[3];
    const float* as1   = (const float*)d_in[4];
    const float* ad1   = (const float*)d_in[5];
    const float* b1    = (const float*)d_in[6];
    const float* W2    = (const float*)d_in[7];
    const float* as2   = (const float*)d_in[8];
    const float* ad2   = (const float*)d_in[9];
    const float* b2    = (const float*)d_in[10];
    const float* fc1w  = (const float*)d_in[11];
    const float* fc1b  = (const float*)d_in[12];
    const float* fc2w  = (const float*)d_in[13];
    const float* fc2b  = (const float*)d_in[14];
    float* out = (float*)d_out;

    __nv_bfloat16 *xwb, *h1h, *w1h, *w2h;
    cudaGetSymbolAddress((void**)&xwb, g_xwb);
    cudaGetSymbolAddress((void**)&h1h, g_h1h);
    cudaGetSymbolAddress((void**)&w1h, g_w1h);
    cudaGetSymbolAddress((void**)&w2h, g_w2h);

    cudaFuncSetAttribute(k_gemm_mma<1>, cudaFuncAttributeMaxDynamicSharedMemorySize, GEMM_DSMEM);
    cudaFuncSetAttribute(k_gemm_mma<0>, cudaFuncAttributeMaxDynamicSharedMemorySize, GEMM_DSMEM);

    const int GEMM_GRID = (N_NODES + MR - 1) / MR;   // 782
    const int WARP_GRID = (N_NODES * 32 + 255) / 256;

    // --- weight transpose + dtype + barrier reset ---
    k_prep<<<449, 256>>>(ei, W1, W2);

    // --- layer 1: CSR build (64 worker blocks) + bf16 GEMM, one kernel ---
    k_gemm_mma<1><<<CSR_NB + GEMM_GRID, 256, GEMM_DSMEM>>>(
        x, nullptr, w1h, N_NODES, IN_F, as1, ad1, xwb, CSR_NB, ei);
    k_gat_agg<<<WARP_GRID, 256>>>(xwb, b1, h1h);

    // --- layer 2 (reads h1h, then agg2 overwrites h1h with layer-2 h) ---
    k_gemm_mma<0><<<GEMM_GRID, 256, GEMM_DSMEM>>>(
        nullptr, h1h, w2h, N_NODES, HID2, as2, ad2, xwb, 0, nullptr);
    k_gat_agg<<<WARP_GRID, 256>>>(xwb, b2, h1h);

    // --- pool + MLP + log_softmax (bf16 h) ---
    k_pool_mlp<<<N_GRAPHS, HID2>>>(h1h, batch, fc1w, fc1b, fc2w, fc2b, out);
}